// round 5
// baseline (speedup 1.0000x reference)
#include <cuda_runtime.h>
#include <cstdint>
#include <math.h>

#define N_NODES 100000
#define N_EDGES 1600000
#define F_IN    256
#define HID     64

// -------- scratch (no device allocations allowed) --------
__device__ int   g_degi  [N_NODES];
__device__ float g_dinv  [N_NODES];
__device__ int   g_rstart[N_NODES];
__device__ int   g_cursor[N_NODES];
__device__ int   g_bsum  [512];
__device__ int   g_csr   [N_EDGES];
__device__ float g_h     [(size_t)N_NODES * HID];
__device__ float g_x2    [(size_t)N_NODES * HID];
__device__ float g_h3    [(size_t)N_NODES * 2];

// -------------------- degree --------------------
__global__ void k_zero_deg(int* __restrict__ deg, int n) {
    int i = blockIdx.x * blockDim.x + threadIdx.x;
    if (i < n) deg[i] = 0;
}

__global__ void k_count_deg(const int* __restrict__ dst, int* __restrict__ deg, int e) {
    int i = blockIdx.x * blockDim.x + threadIdx.x;
    if (i < e) atomicAdd(&deg[dst[i]], 1);
}

// -------------------- two-level exclusive scan over deg --------------------
__global__ void k_scan_block(const int* __restrict__ deg, int* __restrict__ rstart,
                             int* __restrict__ bsum, int n) {
    __shared__ int sm[256];
    int i = blockIdx.x * 256 + threadIdx.x;
    int v = (i < n) ? deg[i] : 0;
    sm[threadIdx.x] = v;
    __syncthreads();
    #pragma unroll
    for (int off = 1; off < 256; off <<= 1) {
        int t = (threadIdx.x >= off) ? sm[threadIdx.x - off] : 0;
        __syncthreads();
        sm[threadIdx.x] += t;
        __syncthreads();
    }
    if (i < n) rstart[i] = sm[threadIdx.x] - v;       // exclusive
    if (threadIdx.x == 255) bsum[blockIdx.x] = sm[255];
}

__global__ void k_scan_sums(int* __restrict__ bsum, int nb) {   // 1 block, 512 threads
    __shared__ int sm[512];
    int v = (threadIdx.x < nb) ? bsum[threadIdx.x] : 0;
    sm[threadIdx.x] = v;
    __syncthreads();
    #pragma unroll
    for (int off = 1; off < 512; off <<= 1) {
        int t = (threadIdx.x >= off) ? sm[threadIdx.x - off] : 0;
        __syncthreads();
        sm[threadIdx.x] += t;
        __syncthreads();
    }
    if (threadIdx.x < nb) bsum[threadIdx.x] = sm[threadIdx.x] - v;  // exclusive
}

// add block offsets + init cursor + compute dinv (fused)
__global__ void k_add_off(int* __restrict__ rstart, int* __restrict__ cursor,
                          const int* __restrict__ bsum, const int* __restrict__ degi,
                          float* __restrict__ dinv, int n) {
    int i = blockIdx.x * blockDim.x + threadIdx.x;
    if (i < n) {
        int v = rstart[i] + bsum[i >> 8];
        rstart[i] = v;
        cursor[i] = v;
        dinv[i] = rsqrtf((float)(degi[i] + 1));   // +1 self-loop
    }
}

__global__ void k_build_csr(const int* __restrict__ src, const int* __restrict__ dst,
                            int* __restrict__ cursor, int* __restrict__ csr, int e) {
    int i = blockIdx.x * blockDim.x + threadIdx.x;
    if (i < e) {
        int p = atomicAdd(&cursor[dst[i]], 1);
        csr[p] = src[i];
    }
}

// -------------------- GEMM: out[m,0:64] = (A[m,:]@W) * (SCALED ? dinv[m] : 1) ------------
// BM=128, BN=64, BK=32; 256 threads; 8x4 per thread; transposed A tile; double-buffered
// through registers (prefetch tile t+1 during tile-t compute).
template <int K, bool SCALED>
__global__ __launch_bounds__(256) void k_gemm(
        const float* __restrict__ A, const float* __restrict__ W,
        const float* __restrict__ dinv, float* __restrict__ out, int M) {
    __shared__ float As[32][132];   // [k][m]
    __shared__ float Bs[32][64];    // [k][n]

    const int tid = threadIdx.x;
    const int tx  = tid & 15;       // col group (4 cols)
    const int ty  = tid >> 4;       // row group (8 rows)
    const int row0 = blockIdx.x * 128;

    int am[4], ak[4];
    #pragma unroll
    for (int l = 0; l < 4; l++) {
        int i = tid + l * 256;
        am[l] = i >> 3;
        ak[l] = (i & 7) << 2;
    }
    int bk[2], bn[2];
    #pragma unroll
    for (int l = 0; l < 2; l++) {
        int i = tid + l * 256;
        bk[l] = i >> 4;
        bn[l] = (i & 15) << 2;
    }

    float4 ra[4], rb[2];
    float acc[8][4] = {};

    #pragma unroll
    for (int l = 0; l < 4; l++) {
        int gr = row0 + am[l];
        ra[l] = (gr < M) ? *(const float4*)(A + (size_t)gr * K + ak[l])
                         : make_float4(0.f, 0.f, 0.f, 0.f);
    }
    #pragma unroll
    for (int l = 0; l < 2; l++)
        rb[l] = *(const float4*)(W + (size_t)bk[l] * 64 + bn[l]);

    constexpr int NT = K / 32;
    #pragma unroll
    for (int t = 0; t < NT; t++) {
        #pragma unroll
        for (int l = 0; l < 4; l++) {
            As[ak[l] + 0][am[l]] = ra[l].x; As[ak[l] + 1][am[l]] = ra[l].y;
            As[ak[l] + 2][am[l]] = ra[l].z; As[ak[l] + 3][am[l]] = ra[l].w;
        }
        #pragma unroll
        for (int l = 0; l < 2; l++)
            *(float4*)&Bs[bk[l]][bn[l]] = rb[l];
        __syncthreads();

        if (t + 1 < NT) {
            int k0 = (t + 1) * 32;
            #pragma unroll
            for (int l = 0; l < 4; l++) {
                int gr = row0 + am[l];
                ra[l] = (gr < M) ? *(const float4*)(A + (size_t)gr * K + k0 + ak[l])
                                 : make_float4(0.f, 0.f, 0.f, 0.f);
            }
            #pragma unroll
            for (int l = 0; l < 2; l++)
                rb[l] = *(const float4*)(W + (size_t)(k0 + bk[l]) * 64 + bn[l]);
        }

        #pragma unroll
        for (int kk = 0; kk < 32; kk++) {
            float4 a0 = *(float4*)&As[kk][ty * 8];
            float4 a1 = *(float4*)&As[kk][ty * 8 + 4];
            float4 b  = *(float4*)&Bs[kk][tx * 4];
            acc[0][0] += a0.x * b.x; acc[0][1] += a0.x * b.y; acc[0][2] += a0.x * b.z; acc[0][3] += a0.x * b.w;
            acc[1][0] += a0.y * b.x; acc[1][1] += a0.y * b.y; acc[1][2] += a0.y * b.z; acc[1][3] += a0.y * b.w;
            acc[2][0] += a0.z * b.x; acc[2][1] += a0.z * b.y; acc[2][2] += a0.z * b.z; acc[2][3] += a0.z * b.w;
            acc[3][0] += a0.w * b.x; acc[3][1] += a0.w * b.y; acc[3][2] += a0.w * b.z; acc[3][3] += a0.w * b.w;
            acc[4][0] += a1.x * b.x; acc[4][1] += a1.x * b.y; acc[4][2] += a1.x * b.z; acc[4][3] += a1.x * b.w;
            acc[5][0] += a1.y * b.x; acc[5][1] += a1.y * b.y; acc[5][2] += a1.y * b.z; acc[5][3] += a1.y * b.w;
            acc[6][0] += a1.z * b.x; acc[6][1] += a1.z * b.y; acc[6][2] += a1.z * b.z; acc[6][3] += a1.z * b.w;
            acc[7][0] += a1.w * b.x; acc[7][1] += a1.w * b.y; acc[7][2] += a1.w * b.z; acc[7][3] += a1.w * b.w;
        }
        __syncthreads();
    }

    #pragma unroll
    for (int i = 0; i < 8; i++) {
        int gr = row0 + ty * 8 + i;
        if (gr < M) {
            float d = SCALED ? dinv[gr] : 1.0f;
            float4 o = make_float4(acc[i][0] * d, acc[i][1] * d, acc[i][2] * d, acc[i][3] * d);
            *(float4*)(out + (size_t)gr * 64 + tx * 4) = o;
        }
    }
}

// -------------------- pull aggregation + fused epilogue (64 features) --------------------
// 16 threads per node, 4 features each; broadcast csr loads, 4 independent gathers in flight.
// NSCALE=true: table h is UNSCALED (layer 1): multiply neighbor rows by dinv[u], self by dinv[node].
// NSCALE=false: table h is already dinv-scaled (layer 2).
template <bool NSCALE>
__global__ void k_pull64(const int* __restrict__ rstart, const int* __restrict__ degi,
                         const int* __restrict__ csr, const float* __restrict__ h,
                         const float* __restrict__ dinv, const float* __restrict__ b,
                         float* __restrict__ out, int n) {
    int gid  = blockIdx.x * blockDim.x + threadIdx.x;
    int node = gid >> 4;
    if (node >= n) return;
    int c = (gid & 15) << 2;

    int s0  = __ldg(&rstart[node]);
    int cnt = __ldg(&degi[node]);
    float dn = dinv[node];

    float4 acc = *(const float4*)(h + (size_t)node * 64 + c);   // self-loop term
    if (NSCALE) { acc.x *= dn; acc.y *= dn; acc.z *= dn; acc.w *= dn; }

    int e = 0;
    for (; e + 4 <= cnt; e += 4) {
        int u0 = __ldg(&csr[s0 + e + 0]);
        int u1 = __ldg(&csr[s0 + e + 1]);
        int u2 = __ldg(&csr[s0 + e + 2]);
        int u3 = __ldg(&csr[s0 + e + 3]);
        float4 v0 = *(const float4*)(h + (size_t)u0 * 64 + c);
        float4 v1 = *(const float4*)(h + (size_t)u1 * 64 + c);
        float4 v2 = *(const float4*)(h + (size_t)u2 * 64 + c);
        float4 v3 = *(const float4*)(h + (size_t)u3 * 64 + c);
        if (NSCALE) {
            float d0 = __ldg(&dinv[u0]), d1 = __ldg(&dinv[u1]);
            float d2 = __ldg(&dinv[u2]), d3 = __ldg(&dinv[u3]);
            acc.x += v0.x * d0 + v1.x * d1 + v2.x * d2 + v3.x * d3;
            acc.y += v0.y * d0 + v1.y * d1 + v2.y * d2 + v3.y * d3;
            acc.z += v0.z * d0 + v1.z * d1 + v2.z * d2 + v3.z * d3;
            acc.w += v0.w * d0 + v1.w * d1 + v2.w * d2 + v3.w * d3;
        } else {
            acc.x += v0.x + v1.x + v2.x + v3.x;
            acc.y += v0.y + v1.y + v2.y + v3.y;
            acc.z += v0.z + v1.z + v2.z + v3.z;
            acc.w += v0.w + v1.w + v2.w + v3.w;
        }
    }
    for (; e < cnt; e++) {
        int u = __ldg(&csr[s0 + e]);
        float4 v = *(const float4*)(h + (size_t)u * 64 + c);
        float d = NSCALE ? __ldg(&dinv[u]) : 1.0f;
        acc.x += v.x * d; acc.y += v.y * d; acc.z += v.z * d; acc.w += v.w * d;
    }

    float4 bb = *(const float4*)(b + c);
    float4 o;
    o.x = fmaxf(dn * acc.x + bb.x, 0.f);
    o.y = fmaxf(dn * acc.y + bb.y, 0.f);
    o.z = fmaxf(dn * acc.z + bb.z, 0.f);
    o.w = fmaxf(dn * acc.w + bb.w, 0.f);
    *(float4*)(out + (size_t)node * 64 + c) = o;
}

// -------------------- layer 3: h3'[m, 0:2] = (A[m,:] @ W3) * dinv[m] --------------------
__global__ void k_gemm3(const float* __restrict__ A, const float* __restrict__ W3,
                        const float* __restrict__ dinv, float* __restrict__ out, int M) {
    __shared__ float w[128];
    if (threadIdx.x < 128) w[threadIdx.x] = W3[threadIdx.x];
    __syncthreads();
    int r = blockIdx.x * blockDim.x + threadIdx.x;
    if (r >= M) return;
    const float* ap = A + (size_t)r * 64;
    float a0 = 0.f, a1 = 0.f;
    #pragma unroll
    for (int k4 = 0; k4 < 64; k4 += 4) {
        float4 a = *(const float4*)(ap + k4);
        a0 += a.x * w[2 * k4 + 0] + a.y * w[2 * k4 + 2] + a.z * w[2 * k4 + 4] + a.w * w[2 * k4 + 6];
        a1 += a.x * w[2 * k4 + 1] + a.y * w[2 * k4 + 3] + a.z * w[2 * k4 + 5] + a.w * w[2 * k4 + 7];
    }
    float d = dinv[r];
    out[2 * r + 0] = a0 * d;
    out[2 * r + 1] = a1 * d;
}

// -------------------- layer 3: pull (2 feats) + log_softmax, 1 thread/node --------------------
__global__ void k_pull2_final(const int* __restrict__ rstart, const int* __restrict__ degi,
                              const int* __restrict__ csr, const float* __restrict__ h3,
                              const float* __restrict__ dinv, const float* __restrict__ b3,
                              float* __restrict__ out, int n) {
    int i = blockIdx.x * blockDim.x + threadIdx.x;
    if (i >= n) return;
    int s0  = __ldg(&rstart[i]);
    int cnt = __ldg(&degi[i]);

    float2 self = *(const float2*)(h3 + (size_t)i * 2);
    float a0 = self.x, a1 = self.y;

    int e = 0;
    for (; e + 4 <= cnt; e += 4) {
        int u0 = __ldg(&csr[s0 + e + 0]);
        int u1 = __ldg(&csr[s0 + e + 1]);
        int u2 = __ldg(&csr[s0 + e + 2]);
        int u3 = __ldg(&csr[s0 + e + 3]);
        float2 v0 = *(const float2*)(h3 + (size_t)u0 * 2);
        float2 v1 = *(const float2*)(h3 + (size_t)u1 * 2);
        float2 v2 = *(const float2*)(h3 + (size_t)u2 * 2);
        float2 v3 = *(const float2*)(h3 + (size_t)u3 * 2);
        a0 += v0.x + v1.x + v2.x + v3.x;
        a1 += v0.y + v1.y + v2.y + v3.y;
    }
    for (; e < cnt; e++) {
        int u = __ldg(&csr[s0 + e]);
        float2 v = *(const float2*)(h3 + (size_t)u * 2);
        a0 += v.x; a1 += v.y;
    }

    float d  = dinv[i];
    float o0 = d * a0 + b3[0];
    float o1 = d * a1 + b3[1];
    float m  = fmaxf(o0, o1);
    float lse = m + logf(expf(o0 - m) + expf(o1 - m));
    out[2 * i + 0] = o0 - lse;
    out[2 * i + 1] = o1 - lse;
}

// -------------------- launch --------------------
extern "C" void kernel_launch(void* const* d_in, const int* in_sizes, int n_in,
                              void* d_out, int out_size) {
    const float* x  = (const float*)d_in[0];
    const int*   ei = (const int*)  d_in[1];
    const float* W1 = (const float*)d_in[2];
    const float* b1 = (const float*)d_in[3];
    const float* W2 = (const float*)d_in[4];
    const float* b2 = (const float*)d_in[5];
    const float* W3 = (const float*)d_in[6];
    const float* b3 = (const float*)d_in[7];

    const int N = in_sizes[0] / F_IN;
    const int E = in_sizes[1] / 2;
    const int* src = ei;
    const int* dst = ei + E;

    int *degi, *rstart, *cursor, *bsum, *csr;
    float *dinv, *h, *x2, *h3;
    cudaGetSymbolAddress((void**)&degi,   g_degi);
    cudaGetSymbolAddress((void**)&rstart, g_rstart);
    cudaGetSymbolAddress((void**)&cursor, g_cursor);
    cudaGetSymbolAddress((void**)&bsum,   g_bsum);
    cudaGetSymbolAddress((void**)&csr,    g_csr);
    cudaGetSymbolAddress((void**)&dinv,   g_dinv);
    cudaGetSymbolAddress((void**)&h,      g_h);
    cudaGetSymbolAddress((void**)&x2,     g_x2);
    cudaGetSymbolAddress((void**)&h3,     g_h3);

    // Lazy side-stream creation: first call is the uncaptured correctness run,
    // so creation happens inside the harness's context and never during capture.
    static bool s_tried = false, s_ok = false;
    static cudaStream_t s_side = nullptr;
    static cudaEvent_t  s_evA = nullptr, s_evB = nullptr;
    if (!s_tried) {
        s_tried = true;
        s_ok = (cudaStreamCreateWithFlags(&s_side, cudaStreamNonBlocking) == cudaSuccess) &&
               (cudaEventCreateWithFlags(&s_evA, cudaEventDisableTiming) == cudaSuccess) &&
               (cudaEventCreateWithFlags(&s_evB, cudaEventDisableTiming) == cudaSuccess);
    }

    const int T  = 256;
    const int NB = (N + 255) / 256;
    const int gemm_blocks = (N + 127) / 128;
    const int pull_blocks = (N * 16 + T - 1) / T;

    const bool fork = s_ok;
    cudaStream_t sp = fork ? s_side : (cudaStream_t)0;   // prep stream
    cudaStream_t ms = (cudaStream_t)0;                   // main stream

    if (fork) {
        cudaEventRecord(s_evA, ms);
        cudaStreamWaitEvent(sp, s_evA, 0);
    }

    // preprocessing on side stream (runs concurrently with layer-1 GEMM)
    k_zero_deg  <<<(N + T - 1) / T, T, 0, sp>>>(degi, N);
    k_count_deg <<<(E + T - 1) / T, T, 0, sp>>>(dst, degi, E);
    k_scan_block<<<NB, 256, 0, sp>>>(degi, rstart, bsum, N);

    // layer-1 GEMM, UNSCALED (independent of preprocessing) — submission 4 = ncu slot
    k_gemm<F_IN, false><<<gemm_blocks, T, 0, ms>>>(x, W1, nullptr, h, N);

    // preprocessing finish
    k_scan_sums <<<1, 512, 0, sp>>>(bsum, NB);
    k_add_off   <<<(N + T - 1) / T, T, 0, sp>>>(rstart, cursor, bsum, degi, dinv, N);
    k_build_csr <<<(E + T - 1) / T, T, 0, sp>>>(src, dst, cursor, csr, E);

    if (fork) {
        cudaEventRecord(s_evB, sp);
        cudaStreamWaitEvent(ms, s_evB, 0);
    }

    // ---- layer 1 aggregation (neighbor-scaled pull, since h is unscaled) ----
    k_pull64<true><<<pull_blocks, T, 0, ms>>>(rstart, degi, csr, h, dinv, b1, x2, N);

    // ---- layer 2 ----
    k_gemm<HID, true><<<gemm_blocks, T, 0, ms>>>(x2, W2, dinv, h, N);
    k_pull64<false><<<pull_blocks, T, 0, ms>>>(rstart, degi, csr, h, dinv, b2, x2, N);

    // ---- layer 3 ----
    k_gemm3      <<<(N + T - 1) / T, T, 0, ms>>>(x2, W3, dinv, h3, N);
    k_pull2_final<<<(N + T - 1) / T, T, 0, ms>>>(rstart, degi, csr, h3, dinv, b3, (float*)d_out, N);
}

// round 6
// speedup vs baseline: 1.3507x; 1.3507x over previous
#include <cuda_runtime.h>
#include <cstdint>
#include <math.h>

#define N_NODES 100000
#define N_EDGES 1600000
#define F_IN    256
#define HID     64

// -------- scratch (no device allocations allowed) --------
__device__ int   g_degi  [N_NODES];
__device__ float g_dinv  [N_NODES];
__device__ int   g_rstart[N_NODES];
__device__ int   g_cursor[N_NODES];
__device__ int   g_bsum  [512];
__device__ int   g_csr   [N_EDGES];
__device__ float g_h     [(size_t)N_NODES * HID];
__device__ float g_x2    [(size_t)N_NODES * HID];
__device__ float g_h3    [(size_t)N_NODES * 2];

// -------------------- degree --------------------
__global__ void k_zero_deg(int* __restrict__ deg, int n) {
    int i = blockIdx.x * blockDim.x + threadIdx.x;
    if (i < n) deg[i] = 0;
}

__global__ void k_count_deg(const int* __restrict__ dst, int* __restrict__ deg, int e) {
    int i = blockIdx.x * blockDim.x + threadIdx.x;
    if (i < e) atomicAdd(&deg[dst[i]], 1);
}

// -------------------- two-level exclusive scan over deg --------------------
__global__ void k_scan_block(const int* __restrict__ deg, int* __restrict__ rstart,
                             int* __restrict__ bsum, int n) {
    __shared__ int sm[256];
    int i = blockIdx.x * 256 + threadIdx.x;
    int v = (i < n) ? deg[i] : 0;
    sm[threadIdx.x] = v;
    __syncthreads();
    #pragma unroll
    for (int off = 1; off < 256; off <<= 1) {
        int t = (threadIdx.x >= off) ? sm[threadIdx.x - off] : 0;
        __syncthreads();
        sm[threadIdx.x] += t;
        __syncthreads();
    }
    if (i < n) rstart[i] = sm[threadIdx.x] - v;       // exclusive
    if (threadIdx.x == 255) bsum[blockIdx.x] = sm[255];
}

__global__ void k_scan_sums(int* __restrict__ bsum, int nb) {   // 1 block, 512 threads
    __shared__ int sm[512];
    int v = (threadIdx.x < nb) ? bsum[threadIdx.x] : 0;
    sm[threadIdx.x] = v;
    __syncthreads();
    #pragma unroll
    for (int off = 1; off < 512; off <<= 1) {
        int t = (threadIdx.x >= off) ? sm[threadIdx.x - off] : 0;
        __syncthreads();
        sm[threadIdx.x] += t;
        __syncthreads();
    }
    if (threadIdx.x < nb) bsum[threadIdx.x] = sm[threadIdx.x] - v;  // exclusive
}

// add block offsets + init cursor + compute dinv (fused)
__global__ void k_add_off(int* __restrict__ rstart, int* __restrict__ cursor,
                          const int* __restrict__ bsum, const int* __restrict__ degi,
                          float* __restrict__ dinv, int n) {
    int i = blockIdx.x * blockDim.x + threadIdx.x;
    if (i < n) {
        int v = rstart[i] + bsum[i >> 8];
        rstart[i] = v;
        cursor[i] = v;
        dinv[i] = rsqrtf((float)(degi[i] + 1));   // +1 self-loop
    }
}

__global__ void k_build_csr(const int* __restrict__ src, const int* __restrict__ dst,
                            int* __restrict__ cursor, int* __restrict__ csr, int e) {
    int i = blockIdx.x * blockDim.x + threadIdx.x;
    if (i < e) {
        int p = atomicAdd(&cursor[dst[i]], 1);
        csr[p] = src[i];
    }
}

// -------------------- helpers for tf32 MMA --------------------
__device__ __forceinline__ uint32_t f2tf32(float f) {
    uint32_t u;
    asm("cvt.rna.tf32.f32 %0, %1;" : "=r"(u) : "f"(f));
    return u;
}

// -------------------- tf32 tensor-core GEMM: out[m,0:64] = A[m,:]@W (unscaled) ------------
// BM=128, BN=64, BK=32; 256 threads = 8 warps (4 M x 2 N), warp tile 32x32.
// mma.sync.m16n8k8 tf32, fp32 accumulate. A converted to tf32 during smem fill.
template <int K>
__global__ __launch_bounds__(256) void k_gemm_tc(
        const float* __restrict__ A, const float* __restrict__ W,
        float* __restrict__ out, int M) {
    __shared__ uint32_t As[128][36];   // [m][k], stride 36: bank = 4g+t, conflict-free frags
    __shared__ uint32_t Bs[32][72];    // [k][n], stride 72: bank = 8t+g, conflict-free frags

    const int tid  = threadIdx.x;
    const int lane = tid & 31;
    const int warp = tid >> 5;
    const int wm   = warp & 3;         // M warp 0..3 (32 rows each)
    const int wn   = warp >> 2;        // N warp 0..1 (32 cols each)
    const int g    = lane >> 2;        // groupID 0..7
    const int t    = lane & 3;         // thread-in-group 0..3
    const int row0 = blockIdx.x * 128;

    float c[2][4][4] = {};             // [m-tile 16][n-tile 8][frag]

    for (int k0 = 0; k0 < K; k0 += 32) {
        // ---- A tile 128x32 -> tf32 smem ----
        #pragma unroll
        for (int l = 0; l < 4; l++) {
            int i  = tid + l * 256;      // 0..1023 float4 slots
            int m  = i >> 3;
            int kk = (i & 7) << 2;
            int gr = row0 + m;
            float4 v = (gr < M) ? *(const float4*)(A + (size_t)gr * K + k0 + kk)
                                : make_float4(0.f, 0.f, 0.f, 0.f);
            uint4 u = make_uint4(f2tf32(v.x), f2tf32(v.y), f2tf32(v.z), f2tf32(v.w));
            *(uint4*)&As[m][kk] = u;
        }
        // ---- B tile 32x64 -> tf32 smem ----
        #pragma unroll
        for (int l = 0; l < 2; l++) {
            int i  = tid + l * 256;
            int kk = i >> 4;
            int n  = (i & 15) << 2;
            float4 v = *(const float4*)(W + (size_t)(k0 + kk) * 64 + n);
            uint4 u = make_uint4(f2tf32(v.x), f2tf32(v.y), f2tf32(v.z), f2tf32(v.w));
            *(uint4*)&Bs[kk][n] = u;
        }
        __syncthreads();

        #pragma unroll
        for (int kc = 0; kc < 4; kc++) {
            int kb = kc * 8;
            // A fragments: 2 m-tiles of 16
            uint32_t a[2][4];
            #pragma unroll
            for (int mt = 0; mt < 2; mt++) {
                int mb = wm * 32 + mt * 16;
                a[mt][0] = As[mb + g     ][kb + t    ];
                a[mt][1] = As[mb + g + 8 ][kb + t    ];
                a[mt][2] = As[mb + g     ][kb + t + 4];
                a[mt][3] = As[mb + g + 8 ][kb + t + 4];
            }
            // B fragments: 4 n-tiles of 8
            uint32_t bfr[4][2];
            #pragma unroll
            for (int j = 0; j < 4; j++) {
                int nb = wn * 32 + j * 8;
                bfr[j][0] = Bs[kb + t    ][nb + g];
                bfr[j][1] = Bs[kb + t + 4][nb + g];
            }
            #pragma unroll
            for (int mt = 0; mt < 2; mt++) {
                #pragma unroll
                for (int j = 0; j < 4; j++) {
                    asm volatile(
                        "mma.sync.aligned.m16n8k8.row.col.f32.tf32.tf32.f32 "
                        "{%0,%1,%2,%3}, {%4,%5,%6,%7}, {%8,%9}, {%0,%1,%2,%3};"
                        : "+f"(c[mt][j][0]), "+f"(c[mt][j][1]),
                          "+f"(c[mt][j][2]), "+f"(c[mt][j][3])
                        : "r"(a[mt][0]), "r"(a[mt][1]), "r"(a[mt][2]), "r"(a[mt][3]),
                          "r"(bfr[j][0]), "r"(bfr[j][1]));
                }
            }
        }
        __syncthreads();
    }

    // epilogue: c0,c1 -> row g; c2,c3 -> row g+8; cols 2t, 2t+1
    #pragma unroll
    for (int mt = 0; mt < 2; mt++) {
        int r0 = row0 + wm * 32 + mt * 16 + g;
        #pragma unroll
        for (int j = 0; j < 4; j++) {
            int col = wn * 32 + j * 8 + 2 * t;
            if (r0 < M)
                *(float2*)(out + (size_t)r0 * 64 + col) = make_float2(c[mt][j][0], c[mt][j][1]);
            if (r0 + 8 < M)
                *(float2*)(out + (size_t)(r0 + 8) * 64 + col) = make_float2(c[mt][j][2], c[mt][j][3]);
        }
    }
}

// -------------------- FFMA GEMM (layer 2): out = (A@W) * dinv[m] ------------
// BM=128, BN=64, BK=32; 256 threads; 8x4 per thread; transposed A tile (R3 version).
template <int K>
__global__ __launch_bounds__(256) void k_gemm_f32(
        const float* __restrict__ A, const float* __restrict__ W,
        const float* __restrict__ dinv, float* __restrict__ out, int M) {
    __shared__ float As[32][132];
    __shared__ float Bs[32][64];

    const int tid = threadIdx.x;
    const int tx  = tid & 15;
    const int ty  = tid >> 4;
    const int row0 = blockIdx.x * 128;

    float acc[8][4] = {};

    for (int k0 = 0; k0 < K; k0 += 32) {
        #pragma unroll
        for (int l = 0; l < 4; l++) {
            int i  = tid + l * 256;
            int m  = i >> 3;
            int kk = (i & 7) << 2;
            float4 v = make_float4(0.f, 0.f, 0.f, 0.f);
            int gr = row0 + m;
            if (gr < M) v = *(const float4*)(A + (size_t)gr * K + k0 + kk);
            As[kk + 0][m] = v.x; As[kk + 1][m] = v.y;
            As[kk + 2][m] = v.z; As[kk + 3][m] = v.w;
        }
        #pragma unroll
        for (int l = 0; l < 2; l++) {
            int i  = tid + l * 256;
            int kk = i >> 4;
            int n  = (i & 15) << 2;
            *(float4*)&Bs[kk][n] = *(const float4*)(W + (size_t)(k0 + kk) * 64 + n);
        }
        __syncthreads();

        #pragma unroll
        for (int kk = 0; kk < 32; kk++) {
            float4 a0 = *(float4*)&As[kk][ty * 8];
            float4 a1 = *(float4*)&As[kk][ty * 8 + 4];
            float4 b  = *(float4*)&Bs[kk][tx * 4];
            acc[0][0] += a0.x * b.x; acc[0][1] += a0.x * b.y; acc[0][2] += a0.x * b.z; acc[0][3] += a0.x * b.w;
            acc[1][0] += a0.y * b.x; acc[1][1] += a0.y * b.y; acc[1][2] += a0.y * b.z; acc[1][3] += a0.y * b.w;
            acc[2][0] += a0.z * b.x; acc[2][1] += a0.z * b.y; acc[2][2] += a0.z * b.z; acc[2][3] += a0.z * b.w;
            acc[3][0] += a0.w * b.x; acc[3][1] += a0.w * b.y; acc[3][2] += a0.w * b.z; acc[3][3] += a0.w * b.w;
            acc[4][0] += a1.x * b.x; acc[4][1] += a1.x * b.y; acc[4][2] += a1.x * b.z; acc[4][3] += a1.x * b.w;
            acc[5][0] += a1.y * b.x; acc[5][1] += a1.y * b.y; acc[5][2] += a1.y * b.z; acc[5][3] += a1.y * b.w;
            acc[6][0] += a1.z * b.x; acc[6][1] += a1.z * b.y; acc[6][2] += a1.z * b.z; acc[6][3] += a1.z * b.w;
            acc[7][0] += a1.w * b.x; acc[7][1] += a1.w * b.y; acc[7][2] += a1.w * b.z; acc[7][3] += a1.w * b.w;
        }
        __syncthreads();
    }

    #pragma unroll
    for (int i = 0; i < 8; i++) {
        int gr = row0 + ty * 8 + i;
        if (gr < M) {
            float d = dinv[gr];
            float4 o = make_float4(acc[i][0] * d, acc[i][1] * d, acc[i][2] * d, acc[i][3] * d);
            *(float4*)(out + (size_t)gr * 64 + tx * 4) = o;
        }
    }
}

// -------------------- pull aggregation + fused epilogue (64 features) --------------------
// 16 threads per node, 4 features each; 4 independent gathers in flight.
// NSCALE=true: table h is UNSCALED (layer 1): neighbor rows scaled by dinv[u], self by dinv[node].
template <bool NSCALE>
__global__ void k_pull64(const int* __restrict__ rstart, const int* __restrict__ degi,
                         const int* __restrict__ csr, const float* __restrict__ h,
                         const float* __restrict__ dinv, const float* __restrict__ b,
                         float* __restrict__ out, int n) {
    int gid  = blockIdx.x * blockDim.x + threadIdx.x;
    int node = gid >> 4;
    if (node >= n) return;
    int c = (gid & 15) << 2;

    int s0  = __ldg(&rstart[node]);
    int cnt = __ldg(&degi[node]);
    float dn = dinv[node];

    float4 acc = *(const float4*)(h + (size_t)node * 64 + c);   // self-loop term
    if (NSCALE) { acc.x *= dn; acc.y *= dn; acc.z *= dn; acc.w *= dn; }

    int e = 0;
    for (; e + 4 <= cnt; e += 4) {
        int u0 = __ldg(&csr[s0 + e + 0]);
        int u1 = __ldg(&csr[s0 + e + 1]);
        int u2 = __ldg(&csr[s0 + e + 2]);
        int u3 = __ldg(&csr[s0 + e + 3]);
        float4 v0 = *(const float4*)(h + (size_t)u0 * 64 + c);
        float4 v1 = *(const float4*)(h + (size_t)u1 * 64 + c);
        float4 v2 = *(const float4*)(h + (size_t)u2 * 64 + c);
        float4 v3 = *(const float4*)(h + (size_t)u3 * 64 + c);
        if (NSCALE) {
            float d0 = __ldg(&dinv[u0]), d1 = __ldg(&dinv[u1]);
            float d2 = __ldg(&dinv[u2]), d3 = __ldg(&dinv[u3]);
            acc.x += v0.x * d0 + v1.x * d1 + v2.x * d2 + v3.x * d3;
            acc.y += v0.y * d0 + v1.y * d1 + v2.y * d2 + v3.y * d3;
            acc.z += v0.z * d0 + v1.z * d1 + v2.z * d2 + v3.z * d3;
            acc.w += v0.w * d0 + v1.w * d1 + v2.w * d2 + v3.w * d3;
        } else {
            acc.x += v0.x + v1.x + v2.x + v3.x;
            acc.y += v0.y + v1.y + v2.y + v3.y;
            acc.z += v0.z + v1.z + v2.z + v3.z;
            acc.w += v0.w + v1.w + v2.w + v3.w;
        }
    }
    for (; e < cnt; e++) {
        int u = __ldg(&csr[s0 + e]);
        float4 v = *(const float4*)(h + (size_t)u * 64 + c);
        float d = NSCALE ? __ldg(&dinv[u]) : 1.0f;
        acc.x += v.x * d; acc.y += v.y * d; acc.z += v.z * d; acc.w += v.w * d;
    }

    float4 bb = *(const float4*)(b + c);
    float4 o;
    o.x = fmaxf(dn * acc.x + bb.x, 0.f);
    o.y = fmaxf(dn * acc.y + bb.y, 0.f);
    o.z = fmaxf(dn * acc.z + bb.z, 0.f);
    o.w = fmaxf(dn * acc.w + bb.w, 0.f);
    *(float4*)(out + (size_t)node * 64 + c) = o;
}

// -------------------- layer 3: h3'[m, 0:2] = (A[m,:] @ W3) * dinv[m] --------------------
__global__ void k_gemm3(const float* __restrict__ A, const float* __restrict__ W3,
                        const float* __restrict__ dinv, float* __restrict__ out, int M) {
    __shared__ float w[128];
    if (threadIdx.x < 128) w[threadIdx.x] = W3[threadIdx.x];
    __syncthreads();
    int r = blockIdx.x * blockDim.x + threadIdx.x;
    if (r >= M) return;
    const float* ap = A + (size_t)r * 64;
    float a0 = 0.f, a1 = 0.f;
    #pragma unroll
    for (int k4 = 0; k4 < 64; k4 += 4) {
        float4 a = *(const float4*)(ap + k4);
        a0 += a.x * w[2 * k4 + 0] + a.y * w[2 * k4 + 2] + a.z * w[2 * k4 + 4] + a.w * w[2 * k4 + 6];
        a1 += a.x * w[2 * k4 + 1] + a.y * w[2 * k4 + 3] + a.z * w[2 * k4 + 5] + a.w * w[2 * k4 + 7];
    }
    float d = dinv[r];
    out[2 * r + 0] = a0 * d;
    out[2 * r + 1] = a1 * d;
}

// -------------------- layer 3: pull (2 feats) + log_softmax, 1 thread/node --------------------
__global__ void k_pull2_final(const int* __restrict__ rstart, const int* __restrict__ degi,
                              const int* __restrict__ csr, const float* __restrict__ h3,
                              const float* __restrict__ dinv, const float* __restrict__ b3,
                              float* __restrict__ out, int n) {
    int i = blockIdx.x * blockDim.x + threadIdx.x;
    if (i >= n) return;
    int s0  = __ldg(&rstart[i]);
    int cnt = __ldg(&degi[i]);

    float2 self = *(const float2*)(h3 + (size_t)i * 2);
    float a0 = self.x, a1 = self.y;

    int e = 0;
    for (; e + 4 <= cnt; e += 4) {
        int u0 = __ldg(&csr[s0 + e + 0]);
        int u1 = __ldg(&csr[s0 + e + 1]);
        int u2 = __ldg(&csr[s0 + e + 2]);
        int u3 = __ldg(&csr[s0 + e + 3]);
        float2 v0 = *(const float2*)(h3 + (size_t)u0 * 2);
        float2 v1 = *(const float2*)(h3 + (size_t)u1 * 2);
        float2 v2 = *(const float2*)(h3 + (size_t)u2 * 2);
        float2 v3 = *(const float2*)(h3 + (size_t)u3 * 2);
        a0 += v0.x + v1.x + v2.x + v3.x;
        a1 += v0.y + v1.y + v2.y + v3.y;
    }
    for (; e < cnt; e++) {
        int u = __ldg(&csr[s0 + e]);
        float2 v = *(const float2*)(h3 + (size_t)u * 2);
        a0 += v.x; a1 += v.y;
    }

    float d  = dinv[i];
    float o0 = d * a0 + b3[0];
    float o1 = d * a1 + b3[1];
    float m  = fmaxf(o0, o1);
    float lse = m + logf(expf(o0 - m) + expf(o1 - m));
    out[2 * i + 0] = o0 - lse;
    out[2 * i + 1] = o1 - lse;
}

// -------------------- launch (single stream, serial) --------------------
extern "C" void kernel_launch(void* const* d_in, const int* in_sizes, int n_in,
                              void* d_out, int out_size) {
    const float* x  = (const float*)d_in[0];
    const int*   ei = (const int*)  d_in[1];
    const float* W1 = (const float*)d_in[2];
    const float* b1 = (const float*)d_in[3];
    const float* W2 = (const float*)d_in[4];
    const float* b2 = (const float*)d_in[5];
    const float* W3 = (const float*)d_in[6];
    const float* b3 = (const float*)d_in[7];

    const int N = in_sizes[0] / F_IN;
    const int E = in_sizes[1] / 2;
    const int* src = ei;
    const int* dst = ei + E;

    int *degi, *rstart, *cursor, *bsum, *csr;
    float *dinv, *h, *x2, *h3;
    cudaGetSymbolAddress((void**)&degi,   g_degi);
    cudaGetSymbolAddress((void**)&rstart, g_rstart);
    cudaGetSymbolAddress((void**)&cursor, g_cursor);
    cudaGetSymbolAddress((void**)&bsum,   g_bsum);
    cudaGetSymbolAddress((void**)&csr,    g_csr);
    cudaGetSymbolAddress((void**)&dinv,   g_dinv);
    cudaGetSymbolAddress((void**)&h,      g_h);
    cudaGetSymbolAddress((void**)&x2,     g_x2);
    cudaGetSymbolAddress((void**)&h3,     g_h3);

    const int T  = 256;
    const int NB = (N + 255) / 256;
    const int gemm_blocks = (N + 127) / 128;
    const int pull_blocks = (N * 16 + T - 1) / T;

    // prep start (independent of gemm1)
    k_zero_deg  <<<(N + T - 1) / T, T>>>(degi, N);
    k_count_deg <<<(E + T - 1) / T, T>>>(dst, degi, E);
    k_scan_block<<<NB, 256>>>(degi, rstart, bsum, N);

    // layer-1 GEMM (tf32 tensor cores, UNSCALED) — submission 4 = ncu slot
    k_gemm_tc<F_IN><<<gemm_blocks, T>>>(x, W1, h, N);

    // prep finish
    k_scan_sums <<<1, 512>>>(bsum, NB);
    k_add_off   <<<(N + T - 1) / T, T>>>(rstart, cursor, bsum, degi, dinv, N);
    k_build_csr <<<(E + T - 1) / T, T>>>(src, dst, cursor, csr, E);

    // ---- layer 1 aggregation (neighbor-scaled pull, since h is unscaled) ----
    k_pull64<true><<<pull_blocks, T>>>(rstart, degi, csr, h, dinv, b1, x2, N);

    // ---- layer 2 (fp32 FFMA) ----
    k_gemm_f32<HID><<<gemm_blocks, T>>>(x2, W2, dinv, h, N);
    k_pull64<false><<<pull_blocks, T>>>(rstart, degi, csr, h, dinv, b2, x2, N);

    // ---- layer 3 ----
    k_gemm3      <<<(N + T - 1) / T, T>>>(x2, W3, dinv, h3, N);
    k_pull2_final<<<(N + T - 1) / T, T>>>(rstart, degi, csr, h3, dinv, b3, (float*)d_out, N);
}